// round 2
// baseline (speedup 1.0000x reference)
#include <cuda_runtime.h>
#include <cstdint>

// Segment-mean over sorted segment ids.
// feats: [N, 128] f32, segment_ids: [N] i32 (sorted ascending), out: [S, 128] f32.
// One CTA per segment. Contiguous segment rows found via binary search.

static constexpr int D = 128;          // feature dim
static constexpr int D4 = D / 4;       // 32 float4 per row
static constexpr int THREADS = 256;
static constexpr int NGROUPS = THREADS / 32;  // 8 rows in flight

__global__ __launch_bounds__(THREADS)
void seg_mean_kernel(const float* __restrict__ feats,
                     const int* __restrict__ seg_ids,
                     float* __restrict__ out,
                     int N) {
    const int s = blockIdx.x;

    __shared__ int sh_bounds[2];  // [start, end)

    // Two threads do the two binary searches (lower_bound for s and s+1).
    if (threadIdx.x < 2) {
        const int target = s + threadIdx.x;  // tid0: s, tid1: s+1
        int lo = 0, hi = N;
        while (lo < hi) {
            int mid = (lo + hi) >> 1;
            if (seg_ids[mid] < target) lo = mid + 1;
            else hi = mid;
        }
        sh_bounds[threadIdx.x] = lo;
    }
    __syncthreads();

    const int start = sh_bounds[0];
    const int end   = sh_bounds[1];
    const int cnt   = end - start;

    const int lane = threadIdx.x & 31;
    const int grp  = threadIdx.x >> 5;   // 0..7

    const float4* __restrict__ f4 = reinterpret_cast<const float4*>(feats);

    float4 acc = make_float4(0.f, 0.f, 0.f, 0.f);

    // 2x unrolled strided walk over this segment's rows: grp g handles rows
    // start+g, start+g+8, ... Each lane loads one float4 (16B), warp = 512B row.
    int r = start + grp;
    for (; r + NGROUPS < end; r += 2 * NGROUPS) {
        float4 a = f4[(size_t)r * D4 + lane];
        float4 b = f4[(size_t)(r + NGROUPS) * D4 + lane];
        acc.x += a.x; acc.y += a.y; acc.z += a.z; acc.w += a.w;
        acc.x += b.x; acc.y += b.y; acc.z += b.z; acc.w += b.w;
    }
    if (r < end) {
        float4 a = f4[(size_t)r * D4 + lane];
        acc.x += a.x; acc.y += a.y; acc.z += a.z; acc.w += a.w;
    }

    // Cross-group reduction: 8 groups x 32 lanes of float4 through smem.
    __shared__ float4 red[NGROUPS][D4];
    red[grp][lane] = acc;
    __syncthreads();

    if (grp == 0) {
        float4 t = red[0][lane];
        #pragma unroll
        for (int g = 1; g < NGROUPS; g++) {
            float4 v = red[g][lane];
            t.x += v.x; t.y += v.y; t.z += v.z; t.w += v.w;
        }
        const float inv = 1.0f / (float)(cnt > 0 ? cnt : 1);
        t.x *= inv; t.y *= inv; t.z *= inv; t.w *= inv;
        reinterpret_cast<float4*>(out)[(size_t)s * D4 + lane] = t;
    }
}

extern "C" void kernel_launch(void* const* d_in, const int* in_sizes, int n_in,
                              void* d_out, int out_size) {
    const float* feats   = (const float*)d_in[0];
    const int*   seg_ids = (const int*)d_in[1];
    float*       out     = (float*)d_out;

    const int N = in_sizes[0] / D;       // number of rows in feats
    const int S = out_size / D;          // number of segments

    seg_mean_kernel<<<S, THREADS>>>(feats, seg_ids, out, N);
}

// round 4
// speedup vs baseline: 1.1247x; 1.1247x over previous
#include <cuda_runtime.h>
#include <cstdint>

// Segment-mean over sorted segment ids.
// feats: [N, 128] f32, segment_ids: [N] i32 (sorted ascending), out: [S, 128] f32.
//
// Two-kernel plan:
//   1) bounds_kernel: one thread per segment boundary does the lower_bound
//      binary search in parallel (removes the ~5kcyc serial pointer chase
//      from every main-kernel CTA's critical path).
//   2) seg_mean_kernel: one CTA per segment, reads its [start,end) with two
//      L2-hit loads, streams rows with 4x-unrolled evict-first float4 loads.

static constexpr int D = 128;          // feature dim
static constexpr int D4 = D / 4;       // 32 float4 per row
static constexpr int THREADS = 256;
static constexpr int NGROUPS = THREADS / 32;  // 8 rows in flight
static constexpr int MAX_SEGS = 1 << 20;

__device__ int g_seg_bounds[MAX_SEGS + 1];

__global__ void bounds_kernel(const int* __restrict__ seg_ids, int N, int S) {
    const int t = blockIdx.x * blockDim.x + threadIdx.x;
    if (t > S) return;
    // lower_bound: first row with seg_id >= t
    int lo = 0, hi = N;
    while (lo < hi) {
        const int mid = (lo + hi) >> 1;
        if (seg_ids[mid] < t) lo = mid + 1;
        else hi = mid;
    }
    g_seg_bounds[t] = lo;
}

__global__ __launch_bounds__(THREADS)
void seg_mean_kernel(const float* __restrict__ feats,
                     float* __restrict__ out) {
    const int s = blockIdx.x;

    const int start = g_seg_bounds[s];
    const int end   = g_seg_bounds[s + 1];
    const int cnt   = end - start;

    const int lane = threadIdx.x & 31;
    const int grp  = threadIdx.x >> 5;   // 0..7

    const float4* __restrict__ f4 = reinterpret_cast<const float4*>(feats);

    float4 acc = make_float4(0.f, 0.f, 0.f, 0.f);

    // 4x unrolled strided walk: grp g handles rows start+g, start+g+8, ...
    // Each lane loads one float4 (16B); a warp covers a full 512B row.
    // __ldcs = evict-first: feats are read exactly once, keep L2 for ids/bounds.
    int r = start + grp;
    for (; r + 3 * NGROUPS < end; r += 4 * NGROUPS) {
        float4 a = __ldcs(&f4[(size_t)r * D4 + lane]);
        float4 b = __ldcs(&f4[(size_t)(r + NGROUPS) * D4 + lane]);
        float4 c = __ldcs(&f4[(size_t)(r + 2 * NGROUPS) * D4 + lane]);
        float4 d = __ldcs(&f4[(size_t)(r + 3 * NGROUPS) * D4 + lane]);
        acc.x += a.x; acc.y += a.y; acc.z += a.z; acc.w += a.w;
        acc.x += b.x; acc.y += b.y; acc.z += b.z; acc.w += b.w;
        acc.x += c.x; acc.y += c.y; acc.z += c.z; acc.w += c.w;
        acc.x += d.x; acc.y += d.y; acc.z += d.z; acc.w += d.w;
    }
    for (; r < end; r += NGROUPS) {
        float4 a = __ldcs(&f4[(size_t)r * D4 + lane]);
        acc.x += a.x; acc.y += a.y; acc.z += a.z; acc.w += a.w;
    }

    // Cross-group reduction: 8 groups x 32 lanes of float4 through smem.
    __shared__ float4 red[NGROUPS][D4];
    red[grp][lane] = acc;
    __syncthreads();

    if (grp == 0) {
        float4 t = red[0][lane];
        #pragma unroll
        for (int g = 1; g < NGROUPS; g++) {
            float4 v = red[g][lane];
            t.x += v.x; t.y += v.y; t.z += v.z; t.w += v.w;
        }
        const float inv = 1.0f / (float)(cnt > 0 ? cnt : 1);
        t.x *= inv; t.y *= inv; t.z *= inv; t.w *= inv;
        reinterpret_cast<float4*>(out)[(size_t)s * D4 + lane] = t;
    }
}

extern "C" void kernel_launch(void* const* d_in, const int* in_sizes, int n_in,
                              void* d_out, int out_size) {
    const float* feats   = (const float*)d_in[0];
    const int*   seg_ids = (const int*)d_in[1];
    float*       out     = (float*)d_out;

    const int N = in_sizes[0] / D;       // number of rows in feats
    const int S = out_size / D;          // number of segments

    const int bthreads = 256;
    const int bblocks  = (S + 1 + bthreads - 1) / bthreads;
    bounds_kernel<<<bblocks, bthreads>>>(seg_ids, N, S);
    seg_mean_kernel<<<S, THREADS>>>(feats, out);
}

// round 6
// speedup vs baseline: 1.1545x; 1.0265x over previous
#include <cuda_runtime.h>
#include <cstdint>

// Segment-mean over sorted segment ids.
// feats: [N, 128] f32, segment_ids: [N] i32 (sorted ascending), out: [S, 128] f32.
//
// Two-kernel plan:
//   1) boundary_kernel: linear scan, one thread per row. Where the id changes
//      from a -> b, write bounds[t] = i for all t in (a, b]. Head threads fill
//      [0, id[0]], the last thread fills (id[N-1], S]. Every bounds entry is
//      written exactly once (empty segments included), ~2us BW-bound instead
//      of the ~9us latency-bound per-segment binary search.
//   2) seg_mean_kernel: one CTA per segment, reads its [start,end) with two
//      L2-hit loads, streams rows with 4x-unrolled evict-first float4 loads.

static constexpr int D = 128;          // feature dim
static constexpr int D4 = D / 4;       // 32 float4 per row
static constexpr int THREADS = 256;
static constexpr int NGROUPS = THREADS / 32;  // 8 rows in flight
static constexpr int MAX_SEGS = 1 << 20;

__device__ int g_seg_bounds[MAX_SEGS + 1];

__global__ void boundary_kernel(const int* __restrict__ seg_ids, int N, int S) {
    const int i = blockIdx.x * blockDim.x + threadIdx.x;
    if (i >= N) return;

    const int b = seg_ids[i];
    if (i == 0) {
        // head: segments 0..b start at row 0
        for (int t = 0; t <= b; t++) g_seg_bounds[t] = 0;
    } else {
        const int a = seg_ids[i - 1];
        if (a != b) {
            // segments a+1..b start at row i (covers empty segments too)
            for (int t = a + 1; t <= b; t++) g_seg_bounds[t] = i;
        }
    }
    if (i == N - 1) {
        // tail: segments b+1..S "start" at N (empty), plus the end sentinel
        for (int t = b + 1; t <= S; t++) g_seg_bounds[t] = N;
    }
}

__global__ __launch_bounds__(THREADS)
void seg_mean_kernel(const float* __restrict__ feats,
                     float* __restrict__ out) {
    const int s = blockIdx.x;

    const int start = g_seg_bounds[s];
    const int end   = g_seg_bounds[s + 1];
    const int cnt   = end - start;

    const int lane = threadIdx.x & 31;
    const int grp  = threadIdx.x >> 5;   // 0..7

    const float4* __restrict__ f4 = reinterpret_cast<const float4*>(feats);

    float4 acc = make_float4(0.f, 0.f, 0.f, 0.f);

    // 4x unrolled strided walk: grp g handles rows start+g, start+g+8, ...
    // Each lane loads one float4 (16B); a warp covers a full 512B row.
    // __ldcs = evict-first: feats are read exactly once, keep L2 for ids/bounds.
    int r = start + grp;
    for (; r + 3 * NGROUPS < end; r += 4 * NGROUPS) {
        float4 a = __ldcs(&f4[(size_t)r * D4 + lane]);
        float4 b = __ldcs(&f4[(size_t)(r + NGROUPS) * D4 + lane]);
        float4 c = __ldcs(&f4[(size_t)(r + 2 * NGROUPS) * D4 + lane]);
        float4 d = __ldcs(&f4[(size_t)(r + 3 * NGROUPS) * D4 + lane]);
        acc.x += a.x; acc.y += a.y; acc.z += a.z; acc.w += a.w;
        acc.x += b.x; acc.y += b.y; acc.z += b.z; acc.w += b.w;
        acc.x += c.x; acc.y += c.y; acc.z += c.z; acc.w += c.w;
        acc.x += d.x; acc.y += d.y; acc.z += d.z; acc.w += d.w;
    }
    for (; r < end; r += NGROUPS) {
        float4 a = __ldcs(&f4[(size_t)r * D4 + lane]);
        acc.x += a.x; acc.y += a.y; acc.z += a.z; acc.w += a.w;
    }

    // Cross-group reduction: 8 groups x 32 lanes of float4 through smem.
    __shared__ float4 red[NGROUPS][D4];
    red[grp][lane] = acc;
    __syncthreads();

    if (grp == 0) {
        float4 t = red[0][lane];
        #pragma unroll
        for (int g = 1; g < NGROUPS; g++) {
            float4 v = red[g][lane];
            t.x += v.x; t.y += v.y; t.z += v.z; t.w += v.w;
        }
        const float inv = 1.0f / (float)(cnt > 0 ? cnt : 1);
        t.x *= inv; t.y *= inv; t.z *= inv; t.w *= inv;
        reinterpret_cast<float4*>(out)[(size_t)s * D4 + lane] = t;
    }
}

extern "C" void kernel_launch(void* const* d_in, const int* in_sizes, int n_in,
                              void* d_out, int out_size) {
    const float* feats   = (const float*)d_in[0];
    const int*   seg_ids = (const int*)d_in[1];
    float*       out     = (float*)d_out;

    const int N = in_sizes[0] / D;       // number of rows in feats
    const int S = out_size / D;          // number of segments

    const int bthreads = 256;
    const int bblocks  = (N + bthreads - 1) / bthreads;
    boundary_kernel<<<bblocks, bthreads>>>(seg_ids, N, S);
    seg_mean_kernel<<<S, THREADS>>>(feats, out);
}

// round 7
// speedup vs baseline: 1.1592x; 1.0041x over previous
#include <cuda_runtime.h>
#include <cstdint>

// Segment-mean over sorted segment ids.
// feats: [N, 128] f32, segment_ids: [N] i32 (sorted ascending), out: [S, 128] f32.
//
// Two-kernel plan:
//   1) boundary_kernel: vectorized linear scan, one thread per 4 rows (int4).
//      Where the id changes a -> b across consecutive rows, write
//      bounds[t] = row for all t in (a, b]. Head fills [0, id[0]], tail fills
//      (id[N-1], S]. Every bounds entry written exactly once (empty segments
//      included). BW-bound (~8MB) instead of latency-bound binary search.
//   2) seg_mean_kernel: one CTA per segment, reads its [start,end) with two
//      L2-hit loads, streams rows with 4x-unrolled evict-first float4 loads.

static constexpr int D = 128;          // feature dim
static constexpr int D4 = D / 4;       // 32 float4 per row
static constexpr int THREADS = 256;
static constexpr int NGROUPS = THREADS / 32;  // 8 rows in flight
static constexpr int MAX_SEGS = 1 << 20;

__device__ int g_seg_bounds[MAX_SEGS + 1];

__global__ void boundary_kernel(const int* __restrict__ seg_ids, int N, int S) {
    const int t = blockIdx.x * blockDim.x + threadIdx.x;
    const int base = t * 4;
    if (base >= N) return;

    if (base + 4 <= N) {
        // Fast path: one int4 load covers ids[base..base+3].
        const int4 v = *reinterpret_cast<const int4*>(seg_ids + base);
        const int id0 = v.x, id1 = v.y, id2 = v.z, id3 = v.w;

        // predecessor id (ids[base-1]); L1-hit from the neighbor's int4
        int prev;
        if (base == 0) {
            // head: segments 0..id0 start at row 0
            for (int q = 0; q <= id0; q++) g_seg_bounds[q] = 0;
            prev = id0;
        } else {
            prev = seg_ids[base - 1];
        }

        if (prev != id0) for (int q = prev + 1; q <= id0; q++) g_seg_bounds[q] = base;
        if (id0  != id1) for (int q = id0  + 1; q <= id1; q++) g_seg_bounds[q] = base + 1;
        if (id1  != id2) for (int q = id1  + 1; q <= id2; q++) g_seg_bounds[q] = base + 2;
        if (id2  != id3) for (int q = id2  + 1; q <= id3; q++) g_seg_bounds[q] = base + 3;

        if (base + 4 == N) {
            // tail: segments id3+1..S "start" at N (empty), plus end sentinel
            for (int q = id3 + 1; q <= S; q++) g_seg_bounds[q] = N;
        }
    } else {
        // Tail remainder (N not divisible by 4): scalar walk.
        int prev;
        if (base == 0) {
            const int id0 = seg_ids[0];
            for (int q = 0; q <= id0; q++) g_seg_bounds[q] = 0;
            prev = id0;
        } else {
            prev = seg_ids[base - 1];
        }
        for (int i = base; i < N; i++) {
            const int cur = seg_ids[i];
            if (prev != cur) for (int q = prev + 1; q <= cur; q++) g_seg_bounds[q] = i;
            prev = cur;
        }
        for (int q = prev + 1; q <= S; q++) g_seg_bounds[q] = N;
    }
}

__global__ __launch_bounds__(THREADS)
void seg_mean_kernel(const float* __restrict__ feats,
                     float* __restrict__ out) {
    const int s = blockIdx.x;

    const int start = g_seg_bounds[s];
    const int end   = g_seg_bounds[s + 1];
    const int cnt   = end - start;

    const int lane = threadIdx.x & 31;
    const int grp  = threadIdx.x >> 5;   // 0..7

    const float4* __restrict__ f4 = reinterpret_cast<const float4*>(feats);

    float4 acc = make_float4(0.f, 0.f, 0.f, 0.f);

    // 4x unrolled strided walk: grp g handles rows start+g, start+g+8, ...
    // Each lane loads one float4 (16B); a warp covers a full 512B row.
    // __ldcs = evict-first: feats are read exactly once, keep L2 for ids/bounds.
    int r = start + grp;
    for (; r + 3 * NGROUPS < end; r += 4 * NGROUPS) {
        float4 a = __ldcs(&f4[(size_t)r * D4 + lane]);
        float4 b = __ldcs(&f4[(size_t)(r + NGROUPS) * D4 + lane]);
        float4 c = __ldcs(&f4[(size_t)(r + 2 * NGROUPS) * D4 + lane]);
        float4 d = __ldcs(&f4[(size_t)(r + 3 * NGROUPS) * D4 + lane]);
        acc.x += a.x; acc.y += a.y; acc.z += a.z; acc.w += a.w;
        acc.x += b.x; acc.y += b.y; acc.z += b.z; acc.w += b.w;
        acc.x += c.x; acc.y += c.y; acc.z += c.z; acc.w += c.w;
        acc.x += d.x; acc.y += d.y; acc.z += d.z; acc.w += d.w;
    }
    for (; r < end; r += NGROUPS) {
        float4 a = __ldcs(&f4[(size_t)r * D4 + lane]);
        acc.x += a.x; acc.y += a.y; acc.z += a.z; acc.w += a.w;
    }

    // Cross-group reduction: 8 groups x 32 lanes of float4 through smem.
    __shared__ float4 red[NGROUPS][D4];
    red[grp][lane] = acc;
    __syncthreads();

    if (grp == 0) {
        float4 t = red[0][lane];
        #pragma unroll
        for (int g = 1; g < NGROUPS; g++) {
            float4 v = red[g][lane];
            t.x += v.x; t.y += v.y; t.z += v.z; t.w += v.w;
        }
        const float inv = 1.0f / (float)(cnt > 0 ? cnt : 1);
        t.x *= inv; t.y *= inv; t.z *= inv; t.w *= inv;
        reinterpret_cast<float4*>(out)[(size_t)s * D4 + lane] = t;
    }
}

extern "C" void kernel_launch(void* const* d_in, const int* in_sizes, int n_in,
                              void* d_out, int out_size) {
    const float* feats   = (const float*)d_in[0];
    const int*   seg_ids = (const int*)d_in[1];
    float*       out     = (float*)d_out;

    const int N = in_sizes[0] / D;       // number of rows in feats
    const int S = out_size / D;          // number of segments

    const int bthreads = 256;
    const int nvec     = (N + 3) / 4;
    const int bblocks  = (nvec + bthreads - 1) / bthreads;
    boundary_kernel<<<bblocks, bthreads>>>(seg_ids, N, S);
    seg_mean_kernel<<<S, THREADS>>>(feats, out);
}